// round 4
// baseline (speedup 1.0000x reference)
#include <cuda_runtime.h>
#include <cstdint>

#define Bn 16
#define IMG (512*512)          // 2^18
#define NPX (Bn*IMG)           // 4194304
#define TPI 256                // (512/32)^2 tiles per image
#define NTILES (Bn*TPI)        // 4096
#define WARPS 16
#define THREADS (WARPS*32)     // 512
#define SM_STRIDE 35           // 34 cols padded to 35
#define SM_SZ (34*SM_STRIDE)
#define MK_STRIDE 33
#define MK_SZ (32*MK_STRIDE)
#define WARP_SMEM (SM_SZ + MK_SZ)
#define SMEM_BYTES (WARPS*WARP_SMEM*4)
#define MAX_PASSES 1300
#define MAX_TILE_ITERS 1024
#define NFLAGS 4096

// ---- device globals (static scratch; no dynamic allocation) ----
__device__ float g_bufA[NPX];          // xh
__device__ float g_bufB[NPX];          // rec2
__device__ float g_bufC[NPX];          // R
__device__ int   g_tile_epoch[NTILES];
__device__ int   g_flag_arr[NFLAGS];
__device__ unsigned g_cc[Bn];
__device__ int g_hasone, g_haszero;
__device__ unsigned g_bar_count = 0;
__device__ volatile unsigned g_bar_gen = 0;

// ---- software grid barrier (all blocks resident: 1 block/SM via smem) ----
__device__ __forceinline__ void grid_sync(int nb) {
    __syncthreads();
    if (threadIdx.x == 0) {
        __threadfence();
        unsigned gen = g_bar_gen;
        unsigned t = atomicAdd(&g_bar_count, 1u);
        if (t == (unsigned)nb - 1u) {
            atomicExch(&g_bar_count, 0u);
            __threadfence();
            g_bar_gen = gen + 1u;
        } else {
            while (g_bar_gen == gen) { __nanosleep(32); }
        }
        __threadfence();
    }
    __syncthreads();
}

__device__ __forceinline__ float f3max(float a, float b, float c) {
    return fmaxf(fmaxf(a, b), c);
}

// MODE 0: marker=x-h[b],  mask=x
// MODE 1: marker=xh-eps,  mask=xh(bufA);  pass1 streams xh -> out
// MODE 2: marker=min(u,Rmax), mask=Rmax=(bufA-bufB>0); pass1 tallies has-one/zero
template<int MODE>
__device__ void process_tile(int t, float* m,
                             const float* x, const float* hh, const float* u,
                             float* out, long long xh_off,
                             volatile float* sm, float* smk,
                             int lane, int epoch, bool first) {
    const int b   = t >> 8;
    const int r   = t & 255;
    const int ty0 = (r >> 4) << 5;
    const int tx0 = (r & 15) << 5;
    const size_t base = ((size_t)b) << 18;
    const float NEGINF = __int_as_float(0xff800000);
    float hv = 0.0f;
    if (MODE == 0) hv = __ldg(hh + b);

    // ---- load marker tile + halo ----
    for (int i = lane; i < 34 * 34; i += 32) {
        int yy = i / 34, xx = i - yy * 34;
        int gy = ty0 + yy - 1, gx = tx0 + xx - 1;
        float v = NEGINF;
        if ((unsigned)gy < 512u && (unsigned)gx < 512u) {
            size_t p = base + ((size_t)gy << 9) + gx;
            if (!first) {
                v = __ldcg(m + p);
            } else if (MODE == 0) {
                v = __ldg(x + p) - hv;
            } else if (MODE == 1) {
                v = __ldcg(g_bufA + p) - 1e-5f;
            } else {
                float rmx = ((__ldcg(g_bufA + p) - __ldcg(g_bufB + p)) > 0.0f) ? 1.0f : 0.0f;
                v = fminf(__ldg(u + p), rmx);
            }
        }
        sm[yy * SM_STRIDE + xx] = v;
    }
    // ---- load mask (interior only) + pass-1 side effects ----
    int lone = 0, lzero = 0;
    for (int i = lane; i < 1024; i += 32) {
        int yy = i >> 5, xx = i & 31;
        size_t p = base + ((size_t)(ty0 + yy) << 9) + (tx0 + xx);
        float mk;
        if (MODE == 0) {
            mk = __ldg(x + p);
        } else if (MODE == 1) {
            mk = __ldcg(g_bufA + p);
            if (first) out[xh_off + (long long)p] = mk;
        } else {
            mk = ((__ldcg(g_bufA + p) - __ldcg(g_bufB + p)) > 0.0f) ? 1.0f : 0.0f;
            if (first) { if (mk != 0.0f) lone = 1; else lzero = 1; }
        }
        smk[yy * MK_STRIDE + xx] = mk;
    }
    if (MODE == 2 && first) {
        if (__any_sync(0xffffffffu, lone)  && lane == 0) atomicOr(&g_hasone, 1);
        if (__any_sync(0xffffffffu, lzero) && lane == 0) atomicOr(&g_haszero, 1);
    }
    __syncwarp();

    // ---- warp-local relaxation to fixpoint (verbatim from passing R2) ----
    int any = 0;
    for (int it = 0; it < MAX_TILE_ITERS; it++) {
        int ch = 0;
        // DOWN sweep: lane = column
        {
            const int xx = lane;
            #pragma unroll 1
            for (int yy = 0; yy < 32; yy++) {
                float up  = f3max(sm[yy*SM_STRIDE + xx], sm[yy*SM_STRIDE + xx + 1], sm[yy*SM_STRIDE + xx + 2]);
                float cur = sm[(yy+1)*SM_STRIDE + xx + 1];
                float nv  = fminf(fmaxf(cur, up), smk[yy*MK_STRIDE + xx]);
                if (nv > cur) { sm[(yy+1)*SM_STRIDE + xx + 1] = nv; ch = 1; }
                __syncwarp();
            }
        }
        // UP sweep
        {
            const int xx = lane;
            #pragma unroll 1
            for (int yy = 31; yy >= 0; yy--) {
                float dn  = f3max(sm[(yy+2)*SM_STRIDE + xx], sm[(yy+2)*SM_STRIDE + xx + 1], sm[(yy+2)*SM_STRIDE + xx + 2]);
                float cur = sm[(yy+1)*SM_STRIDE + xx + 1];
                float nv  = fminf(fmaxf(cur, dn), smk[yy*MK_STRIDE + xx]);
                if (nv > cur) { sm[(yy+1)*SM_STRIDE + xx + 1] = nv; ch = 1; }
                __syncwarp();
            }
        }
        // RIGHT sweep: lane = row
        {
            const int yy = lane;
            #pragma unroll 1
            for (int xx = 0; xx < 32; xx++) {
                float lf  = f3max(sm[yy*SM_STRIDE + xx], sm[(yy+1)*SM_STRIDE + xx], sm[(yy+2)*SM_STRIDE + xx]);
                float cur = sm[(yy+1)*SM_STRIDE + xx + 1];
                float nv  = fminf(fmaxf(cur, lf), smk[yy*MK_STRIDE + xx]);
                if (nv > cur) { sm[(yy+1)*SM_STRIDE + xx + 1] = nv; ch = 1; }
                __syncwarp();
            }
        }
        // LEFT sweep
        {
            const int yy = lane;
            #pragma unroll 1
            for (int xx = 31; xx >= 0; xx--) {
                float rt  = f3max(sm[yy*SM_STRIDE + xx + 2], sm[(yy+1)*SM_STRIDE + xx + 2], sm[(yy+2)*SM_STRIDE + xx + 2]);
                float cur = sm[(yy+1)*SM_STRIDE + xx + 1];
                float nv  = fminf(fmaxf(cur, rt), smk[yy*MK_STRIDE + xx]);
                if (nv > cur) { sm[(yy+1)*SM_STRIDE + xx + 1] = nv; ch = 1; }
                __syncwarp();
            }
        }
        if (__any_sync(0xffffffffu, ch)) any = 1; else break;
    }

    if (any || first) {   // pass 1 must materialize the computed marker
        for (int i = lane; i < 1024; i += 32) {
            int yy = i >> 5, xx = i & 31;
            __stcg(m + base + ((size_t)(ty0 + yy) << 9) + (tx0 + xx),
                   sm[(yy+1)*SM_STRIDE + xx + 1]);
        }
    }
    if (any && lane == 0) {
        ((volatile int*)g_tile_epoch)[t] = epoch;
        ((volatile int*)g_flag_arr)[epoch] = 1;
    }
}

// ---- global reconstruction: repeat passes until no tile changes ----
template<int MODE>
__device__ void reconstruct(float* m,
                            const float* x, const float* hh, const float* u,
                            float* out, long long xh_off,
                            int nb, int& epoch,
                            volatile float* sm, float* smk) {
    const int wid  = threadIdx.x >> 5;
    const int lane = threadIdx.x & 31;
    const int wslots = nb * WARPS;
    bool first = true;
    for (int pass = 0; pass < MAX_PASSES; pass++) {
        epoch++;
        for (int t = blockIdx.x * WARPS + wid; t < NTILES; t += wslots) {
            if (!first) {
                int need = 0;
                if (lane < 9 && lane != 4) {      // 8 neighbor tiles
                    int dy = lane / 3 - 1, dx = lane % 3 - 1;
                    int b = t >> 8, r = t & 255;
                    int ny = (r >> 4) + dy, nx = (r & 15) + dx;
                    if ((unsigned)ny < 16u && (unsigned)nx < 16u)
                        need = (((volatile int*)g_tile_epoch)[(b << 8) + (ny << 4) + nx] >= (epoch - 1));
                }
                if (!__any_sync(0xffffffffu, need)) continue;
            }
            process_tile<MODE>(t, m, x, hh, u, out, xh_off, sm, smk, lane, epoch, first);
        }
        grid_sync(nb);
        // flag index `epoch` is written only before this barrier, never reused
        if (!((volatile int*)g_flag_arr)[epoch]) break;
        first = false;
    }
}

__global__ void __launch_bounds__(THREADS, 1)
mega(const float* __restrict__ x, const float* __restrict__ hh,
     const float* __restrict__ u, float* __restrict__ out,
     int nb, long long xh_off, int write_cc)
{
    extern __shared__ float dynsm[];
    const int wid  = threadIdx.x >> 5;
    const int lane = threadIdx.x & 31;
    volatile float* sm = dynsm + (size_t)wid * WARP_SMEM;
    float* smk = (float*)(dynsm + (size_t)wid * WARP_SMEM + SM_SZ);
    const int gtid = blockIdx.x * THREADS + threadIdx.x;
    const int nt   = nb * THREADS;

    // ---- reset per-launch state (tiny; marker init is fused into pass 1) ----
    for (int i = gtid; i < NFLAGS; i += nt) g_flag_arr[i] = 0;
    for (int i = gtid; i < NTILES; i += nt) g_tile_epoch[i] = 0;
    if (gtid < Bn) g_cc[gtid] = 0u;
    if (gtid == 0) { g_hasone = 0; g_haszero = 0; }
    grid_sync(nb);

    int epoch = 0;
    // xh = reconstruct(x - h, x)
    reconstruct<0>(g_bufA, x, hh, u, out, xh_off, nb, epoch, sm, smk);
    // rec2 = reconstruct(xh - eps, xh); pass 1 streams xh into out
    reconstruct<1>(g_bufB, x, hh, u, out, xh_off, nb, epoch, sm, smk);
    // R = reconstruct(min(u,Rmax), Rmax); Rmax recomputed from bufA/bufB
    reconstruct<2>(g_bufC, x, hh, u, out, xh_off, nb, epoch, sm, smk);

    // ---- Detection = (u == R); CC[b] via ballot+popc ----
    __shared__ unsigned s_cnt[Bn];
    if (threadIdx.x < Bn) s_cnt[threadIdx.x] = 0u;
    __syncthreads();
    for (int i = gtid; i < NPX; i += nt) {   // NPX, nt, warps all 32-aligned
        unsigned mball = __ballot_sync(0xffffffffu, u[i] == __ldcg(g_bufC + i));
        if (lane == 0 && mball) atomicAdd(&s_cnt[i >> 18], (unsigned)__popc(mball));
    }
    __syncthreads();
    if (threadIdx.x < Bn && s_cnt[threadIdx.x])
        atomicAdd(&g_cc[threadIdx.x], s_cnt[threadIdx.x]);
    grid_sync(nb);

    if (write_cc && blockIdx.x == 0 && threadIdx.x < Bn) {
        int ho = ((volatile int*)&g_hasone)[0];
        int hz = ((volatile int*)&g_haszero)[0];
        float d  = (ho && hz) ? 1.0f : 0.0f;   // max(Rmax) - min(Rmax)
        float cc = (float)((volatile unsigned*)g_cc)[threadIdx.x];
        out[threadIdx.x] = fminf(cc, 100.0f * d * cc);
    }
}

extern "C" void kernel_launch(void* const* d_in, const int* in_sizes, int n_in,
                              void* d_out, int out_size) {
    const float* x = (const float*)d_in[0];
    const float* h = (const float*)d_in[1];
    const float* u = (const float*)d_in[2];
    float* out = (float*)d_out;

    int dev = 0;
    cudaGetDevice(&dev);
    int sms = 0;
    cudaDeviceGetAttribute(&sms, cudaDevAttrMultiProcessorCount, dev);
    if (sms <= 0) sms = 148;

    cudaFuncSetAttribute(mega, cudaFuncAttributeMaxDynamicSharedMemorySize, SMEM_BYTES);
    int occ = 0;
    cudaOccupancyMaxActiveBlocksPerMultiprocessor(&occ, mega, THREADS, SMEM_BYTES);
    if (occ < 1) occ = 1;
    int nb = sms * occ;   // all blocks resident -> software grid barrier is safe

    long long xh_off = (long long)out_size - NPX;   // tuple layout: [CC_(16) | xh(N)]
    int write_cc = (xh_off >= Bn) ? 1 : 0;
    if (xh_off < 0) xh_off = 0;

    mega<<<nb, THREADS, SMEM_BYTES>>>(x, h, u, out, nb, xh_off, write_cc);
}

// round 6
// speedup vs baseline: 1.1251x; 1.1251x over previous
#include <cuda_runtime.h>
#include <cstdint>

#define Bn 16
#define IMG (512*512)           // 2^18
#define NPX (Bn*IMG)            // 4194304
#define RS 128                  // region size
#define RPI 16                  // 4x4 regions per image
#define NREG (Bn*RPI)           // 256
#define THREADS 512
#define ST 131                  // smem row stride (gcd(131,32)=1)
#define MS_WORDS (130*ST)
#define KS_WORDS (128*ST)
#define SMEM_BYTES ((MS_WORDS + KS_WORDS)*4)   // ~135 KB
#define MAX_BLOCK_ITERS 4096
#define MAX_PASSES 1300
#define NFLAGS 4096

// ---- device globals (static scratch) ----
__device__ float g_bufA[NPX];          // xh
__device__ float g_bufB[NPX];          // rec2 -> Rmax
__device__ float g_bufC[NPX];          // M -> R
__device__ int   g_reg_epoch[NREG];
__device__ int   g_reg_trunc[NREG];
__device__ int   g_flag_arr[NFLAGS];
__device__ unsigned g_cc[Bn];
__device__ int g_hasone, g_haszero;
__device__ unsigned g_bar_count = 0;
__device__ volatile unsigned g_bar_gen = 0;

// ---- software grid barrier (all blocks resident: 1 block/SM via smem) ----
__device__ __forceinline__ void grid_sync(int nb) {
    __syncthreads();
    if (threadIdx.x == 0) {
        __threadfence();
        unsigned gen = g_bar_gen;
        unsigned t = atomicAdd(&g_bar_count, 1u);
        if (t == (unsigned)nb - 1u) {
            atomicExch(&g_bar_count, 0u);
            __threadfence();
            g_bar_gen = gen + 1u;
        } else {
            while (g_bar_gen == gen) { __nanosleep(32); }
        }
        __threadfence();
    }
    __syncthreads();
}

__device__ __forceinline__ float f3max(float a, float b, float c) {
    return fmaxf(fmaxf(a, b), c);
}

// ---- one 4-directional sweep of a 32x32 subtile inside the shared region ----
// returns PER-LANE changed flag; caller must warp-reduce with __any_sync.
__device__ int relax_once(volatile float* MS, const float* KS,
                          int wy, int wx, int lane) {
    int ch = 0;
    // DOWN (lane = column)
    {
        const int c = (wx << 5) + lane + 1;
        #pragma unroll 1
        for (int yy = 0; yy < 32; yy++) {
            const int row = (wy << 5) + yy + 1;
            float up  = f3max(MS[(row-1)*ST + c-1], MS[(row-1)*ST + c], MS[(row-1)*ST + c+1]);
            float cur = MS[row*ST + c];
            float nv  = fminf(fmaxf(cur, up), KS[(row-1)*ST + (c-1)]);
            if (nv > cur) { MS[row*ST + c] = nv; ch = 1; }
            __syncwarp();
        }
    }
    // UP
    {
        const int c = (wx << 5) + lane + 1;
        #pragma unroll 1
        for (int yy = 31; yy >= 0; yy--) {
            const int row = (wy << 5) + yy + 1;
            float dn  = f3max(MS[(row+1)*ST + c-1], MS[(row+1)*ST + c], MS[(row+1)*ST + c+1]);
            float cur = MS[row*ST + c];
            float nv  = fminf(fmaxf(cur, dn), KS[(row-1)*ST + (c-1)]);
            if (nv > cur) { MS[row*ST + c] = nv; ch = 1; }
            __syncwarp();
        }
    }
    // RIGHT (lane = row; stride 131 -> conflict-free)
    {
        const int row = (wy << 5) + lane + 1;
        #pragma unroll 1
        for (int xx = 0; xx < 32; xx++) {
            const int c = (wx << 5) + xx + 1;
            float lf  = f3max(MS[(row-1)*ST + c-1], MS[row*ST + c-1], MS[(row+1)*ST + c-1]);
            float cur = MS[row*ST + c];
            float nv  = fminf(fmaxf(cur, lf), KS[(row-1)*ST + (c-1)]);
            if (nv > cur) { MS[row*ST + c] = nv; ch = 1; }
            __syncwarp();
        }
    }
    // LEFT
    {
        const int row = (wy << 5) + lane + 1;
        #pragma unroll 1
        for (int xx = 31; xx >= 0; xx--) {
            const int c = (wx << 5) + xx + 1;
            float rt  = f3max(MS[(row-1)*ST + c+1], MS[row*ST + c+1], MS[(row+1)*ST + c+1]);
            float cur = MS[row*ST + c];
            float nv  = fminf(fmaxf(cur, rt), KS[(row-1)*ST + (c-1)]);
            if (nv > cur) { MS[row*ST + c] = nv; ch = 1; }
            __syncwarp();
        }
    }
    return ch;
}

// ---- reconstruct(m, mask): block-per-region fixpoint in smem ----
__device__ void reconstruct(float* m, const float* mask, int nb, int& epoch,
                            volatile float* MS, float* KS) {
    const int tid  = threadIdx.x;
    const int wid  = tid >> 5;
    const int lane = tid & 31;
    const int wy   = wid >> 2, wx = wid & 3;
    __shared__ int s_sub[2][16];
    __shared__ int s_need, s_regch;
    const float NEGINF = __int_as_float(0xff800000);

    bool first = true;
    for (int pass = 0; pass < MAX_PASSES; pass++) {
        epoch++;
        for (int r = blockIdx.x; r < NREG; r += nb) {
            const int b  = r >> 4, idx = r & 15;
            const int ry = idx >> 2, rx = idx & 3;
            if (!first) {
                if (tid == 0) s_need = 0;
                __syncthreads();
                if (tid < 9) {
                    if (tid == 4) {
                        if (((volatile int*)g_reg_trunc)[r] >= epoch - 1) s_need = 1;
                    } else {
                        int dy = tid / 3 - 1, dx = tid % 3 - 1;
                        int ny = ry + dy, nx = rx + dx;
                        if ((unsigned)ny < 4u && (unsigned)nx < 4u)
                            if (((volatile int*)g_reg_epoch)[(b << 4) + (ny << 2) + nx] >= epoch - 1)
                                s_need = 1;
                    }
                }
                __syncthreads();
                if (!s_need) continue;
            }
            const size_t base = ((size_t)b) << 18;
            const int gy0 = ry * RS, gx0 = rx * RS;

            // load marker region + 1-px halo (out-of-image -> -inf)
            for (int i = tid; i < 130 * 130; i += THREADS) {
                int yy = i / 130, xx = i - yy * 130;
                int gy = gy0 + yy - 1, gx = gx0 + xx - 1;
                float v = NEGINF;
                if ((unsigned)gy < 512u && (unsigned)gx < 512u)
                    v = __ldcg(m + base + ((size_t)gy << 9) + gx);
                MS[yy * ST + xx] = v;
            }
            // load mask (interior)
            for (int i = tid; i < 128 * 128; i += THREADS) {
                int yy = i >> 7, xx = i & 127;
                KS[yy * ST + xx] = __ldcg(mask + base + ((size_t)(gy0 + yy) << 9) + (gx0 + xx));
            }
            if (tid == 0) s_regch = 0;
            __syncthreads();

            // block-level fixpoint: warps relax subtiles, halos via smem
            int capped = 1;
            for (int it = 0; it < MAX_BLOCK_ITERS; it++) {
                const int p = it & 1, q = 1 - p;
                int dirty;
                if (it == 0) dirty = 1;
                else {
                    dirty = 0;
                    #pragma unroll
                    for (int dy = -1; dy <= 1; dy++)
                        #pragma unroll
                        for (int dx = -1; dx <= 1; dx++) {
                            int ny = wy + dy, nx = wx + dx;
                            if ((unsigned)ny < 4u && (unsigned)nx < 4u)
                                dirty |= s_sub[q][(ny << 2) + nx];
                        }
                }
                int ch = 0;
                if (dirty) ch = relax_once(MS, KS, wy, wx, lane);
                ch = __any_sync(0xffffffffu, ch);   // THE FIX: warp-wide changed flag
                if (lane == 0) { s_sub[p][wid] = ch; if (ch) s_regch = 1; }
                __syncthreads();
                int any = 0;
                #pragma unroll
                for (int w = 0; w < 16; w++) any |= s_sub[p][w];
                if (!any) { capped = 0; break; }
            }

            if (s_regch) {
                for (int i = tid; i < 128 * 128; i += THREADS) {
                    int yy = i >> 7, xx = i & 127;
                    __stcg(m + base + ((size_t)(gy0 + yy) << 9) + (gx0 + xx),
                           MS[(yy + 1) * ST + (xx + 1)]);
                }
                if (tid == 0) {
                    ((volatile int*)g_reg_epoch)[r] = epoch;
                    ((volatile int*)g_flag_arr)[epoch] = 1;
                }
            }
            if (capped && tid == 0) ((volatile int*)g_reg_trunc)[r] = epoch;
            __syncthreads();   // protect smem reuse for next region
        }
        grid_sync(nb);
        // flag index `epoch` written only before this barrier, never reused
        if (!((volatile int*)g_flag_arr)[epoch]) break;
        first = false;
    }
}

__global__ void __launch_bounds__(THREADS, 1)
mega(const float* __restrict__ x, const float* __restrict__ hh,
     const float* __restrict__ u, float* __restrict__ out,
     int nb, long long xh_off, int write_cc)
{
    extern __shared__ float dynsm[];
    volatile float* MS = dynsm;
    float* KS = dynsm + MS_WORDS;
    const int lane = threadIdx.x & 31;
    const int gtid = blockIdx.x * THREADS + threadIdx.x;
    const int nt   = nb * THREADS;

    // reset per-launch state; marker = x - h[b]  (coalesced streams)
    for (int i = gtid; i < NFLAGS; i += nt) g_flag_arr[i] = 0;
    for (int i = gtid; i < NREG; i += nt) { g_reg_epoch[i] = 0; g_reg_trunc[i] = 0; }
    if (gtid < Bn) g_cc[gtid] = 0u;
    if (gtid == 0) { g_hasone = 0; g_haszero = 0; }
    for (int i = gtid; i < NPX; i += nt) {
        float hv = __ldg(hh + (i >> 18));
        __stcg(g_bufA + i, x[i] - hv);
    }
    grid_sync(nb);

    int epoch = 0;
    // xh = reconstruct(x - h, x)
    reconstruct(g_bufA, x, nb, epoch, MS, KS);

    // write xh to output; marker2 = xh - eps
    for (int i = gtid; i < NPX; i += nt) {
        float v = __ldcg(g_bufA + i);
        out[xh_off + i] = v;
        __stcg(g_bufB + i, v - 1e-5f);
    }
    grid_sync(nb);
    // rec2 = reconstruct(xh - eps, xh)
    reconstruct(g_bufB, g_bufA, nb, epoch, MS, KS);

    // Rmax = (xh - rec2 > 0); M = min(u, Rmax); global has-one/has-zero
    int one = 0, zero = 0;
    for (int i = gtid; i < NPX; i += nt) {
        float rec = __ldcg(g_bufB + i);
        float xh  = __ldcg(g_bufA + i);
        float rmx = ((xh - rec) > 0.0f) ? 1.0f : 0.0f;
        if (rmx != 0.0f) one = 1; else zero = 1;
        __stcg(g_bufB + i, rmx);
        __stcg(g_bufC + i, fminf(u[i], rmx));
    }
    if (__any_sync(0xffffffffu, one)  && lane == 0) atomicOr(&g_hasone, 1);
    if (__any_sync(0xffffffffu, zero) && lane == 0) atomicOr(&g_haszero, 1);
    grid_sync(nb);
    // R = reconstruct(M, Rmax)
    reconstruct(g_bufC, g_bufB, nb, epoch, MS, KS);

    // Detection = (u == R); CC[b] via ballot+popc (exact integer counts)
    __shared__ unsigned s_cnt[Bn];
    if (threadIdx.x < Bn) s_cnt[threadIdx.x] = 0u;
    __syncthreads();
    for (int i = gtid; i < NPX; i += nt) {
        unsigned mball = __ballot_sync(0xffffffffu, u[i] == __ldcg(g_bufC + i));
        if (lane == 0 && mball) atomicAdd(&s_cnt[i >> 18], (unsigned)__popc(mball));
    }
    __syncthreads();
    if (threadIdx.x < Bn && s_cnt[threadIdx.x])
        atomicAdd(&g_cc[threadIdx.x], s_cnt[threadIdx.x]);
    grid_sync(nb);

    if (write_cc && blockIdx.x == 0 && threadIdx.x < Bn) {
        int ho = ((volatile int*)&g_hasone)[0];
        int hz = ((volatile int*)&g_haszero)[0];
        float d  = (ho && hz) ? 1.0f : 0.0f;   // max(Rmax) - min(Rmax)
        float cc = (float)((volatile unsigned*)g_cc)[threadIdx.x];
        out[threadIdx.x] = fminf(cc, 100.0f * d * cc);
    }
}

extern "C" void kernel_launch(void* const* d_in, const int* in_sizes, int n_in,
                              void* d_out, int out_size) {
    const float* x = (const float*)d_in[0];
    const float* h = (const float*)d_in[1];
    const float* u = (const float*)d_in[2];
    float* out = (float*)d_out;

    int dev = 0;
    cudaGetDevice(&dev);
    int sms = 0;
    cudaDeviceGetAttribute(&sms, cudaDevAttrMultiProcessorCount, dev);
    if (sms <= 0) sms = 148;

    cudaFuncSetAttribute(mega, cudaFuncAttributeMaxDynamicSharedMemorySize, SMEM_BYTES);
    int occ = 0;
    cudaOccupancyMaxActiveBlocksPerMultiprocessor(&occ, mega, THREADS, SMEM_BYTES);
    if (occ < 1) occ = 1;
    int nb = sms * occ;   // all blocks resident -> software grid barrier safe

    long long xh_off = (long long)out_size - NPX;   // [CC_(16) | xh(N)]
    int write_cc = (xh_off >= Bn) ? 1 : 0;
    if (xh_off < 0) xh_off = 0;

    mega<<<nb, THREADS, SMEM_BYTES>>>(x, h, u, out, nb, xh_off, write_cc);
}